// round 4
// baseline (speedup 1.0000x reference)
#include <cuda_runtime.h>
#include <stdint.h>
#include <math.h>

#define BATCH 32
#define CHAN  256
#define HH    56
#define WW    56
#define S     (HH*WW)        // 3136
#define S4    (S/4)          // 784
#define QSPLIT 16
#define CQ    (CHAN/QSPLIT)  // 16
#define RNUM  1568           // removed_num = round(3136*0.5)
#define RB    7              // row-blocks per batch (8 rows each)

// scratch (no cudaMalloc allowed)
__device__ __align__(16) float        g_part_max[QSPLIT*BATCH*S];
__device__ __align__(16) float        g_part_sum[QSPLIT*BATCH*S];
__device__ __align__(16) unsigned int g_uvals[BATCH*S];
__device__ unsigned int g_T[BATCH];
__device__ int          g_bound[BATCH];

// ---------------------------------------------------------------------------
// Kernel 1: partial channel max/sum. 1568 blocks x 256 threads (full occ).
// Read-roofline kernel (~103 MB in).
// ---------------------------------------------------------------------------
__global__ void pool_partial(const float* __restrict__ x) {
    int gid = blockIdx.x * blockDim.x + threadIdx.x;
    int q   = gid / (BATCH * S4);
    int rem = gid % (BATCH * S4);
    int b   = rem / S4;
    int s4  = rem % S4;

    const float4* p = reinterpret_cast<const float4*>(x)
                    + (size_t)(b * CHAN + q * CQ) * S4 + s4;

    float4 mx = make_float4(-INFINITY, -INFINITY, -INFINITY, -INFINITY);
    float4 sm = make_float4(0.f, 0.f, 0.f, 0.f);

    #pragma unroll
    for (int c = 0; c < CQ; ++c) {
        float4 v = __ldg(p + (size_t)c * S4);
        mx.x = fmaxf(mx.x, v.x); mx.y = fmaxf(mx.y, v.y);
        mx.z = fmaxf(mx.z, v.z); mx.w = fmaxf(mx.w, v.w);
        sm.x += v.x; sm.y += v.y; sm.z += v.z; sm.w += v.w;
    }

    int o = (q * BATCH + b) * S4 + s4;
    reinterpret_cast<float4*>(g_part_max)[o] = mx;
    reinterpret_cast<float4*>(g_part_sum)[o] = sm;
}

// ---------------------------------------------------------------------------
// Kernel 2: combine partials + 3x3 conv + sigmoid -> g_uvals. 224 blocks
// (BATCH*RB), 448 threads; each block owns an 8-row slab + 1-row halo.
// Partials are L2-hot (12.8 MB), full-chip parallel.
// ---------------------------------------------------------------------------
__global__ void __launch_bounds__(448) conv_sig(const float* __restrict__ w) {
    __shared__ float pm[10 * WW];
    __shared__ float pa[10 * WW];
    __shared__ float ws[18];

    const int b  = blockIdx.x / RB;
    const int rb = blockIdx.x % RB;
    const int t  = threadIdx.x;
    const int row0 = rb * 8 - 1;            // global row of smem row 0

    if (t < 18) ws[t] = w[t];

    const float inv = 1.0f / (float)CHAN;
    for (int j = t; j < 10 * WW; j += 448) {
        int grow = row0 + j / WW;
        int col  = j % WW;
        float mx = 0.f, sm = 0.f;
        if (grow >= 0 && grow < HH) {
            int base = grow * WW + col;
            mx = -INFINITY;
            #pragma unroll
            for (int q = 0; q < QSPLIT; ++q) {
                int o = (q * BATCH + b) * S + base;
                mx = fmaxf(mx, g_part_max[o]);
                sm += g_part_sum[o];
            }
            sm *= inv;
        }
        pm[j] = mx;
        pa[j] = sm;
    }
    __syncthreads();

    // one output per thread: 8 rows x 56 cols = 448
    const int ohl = t / WW;                 // 0..7 local row
    const int ow  = t % WW;
    const int oh  = rb * 8 + ohl;

    float acc = 0.f;
    #pragma unroll
    for (int ky = 0; ky < 3; ++ky) {
        int ih = oh + ky - 1;
        if (ih < 0 || ih >= HH) continue;
        int lr = ohl + ky;                  // smem row (global ih - row0)
        #pragma unroll
        for (int kx = 0; kx < 3; ++kx) {
            int iw = ow + kx - 1;
            if (iw < 0 || iw >= WW) continue;
            int ii = lr * WW + iw;
            acc = fmaf(pm[ii], ws[ky * 3 + kx], acc);
            acc = fmaf(pa[ii], ws[9 + ky * 3 + kx], acc);
        }
    }
    float y = 1.0f / (1.0f + expf(-acc));
    g_uvals[b * S + oh * WW + ow] = __float_as_uint(y);
}

// ---------------------------------------------------------------------------
// Kernel 3: per-batch exact radix select of rank RNUM-1. Emits threshold T
// and tie index bound. One block per batch, 1024 threads. Values L2-hot.
// ---------------------------------------------------------------------------
__global__ void __launch_bounds__(1024, 1) select_thresh() {
    __shared__ unsigned int uvals[S];
    __shared__ int hist[256];
    __shared__ int warpTot[8];
    __shared__ unsigned int s_prefix;
    __shared__ int s_r, s_less;
    __shared__ int tieIdx[256];
    __shared__ int tieCount;

    const int b = blockIdx.x;
    const int t = threadIdx.x;
    const int lane = t & 31;

    for (int i = t; i < S; i += 1024) uvals[i] = g_uvals[b * S + i];
    if (t == 0) { s_r = RNUM - 1; s_less = 0; s_prefix = 0u; tieCount = 0; }
    __syncthreads();

    #pragma unroll
    for (int pass = 0; pass < 4; ++pass) {
        const int shift = 24 - 8 * pass;
        if (t < 256) hist[t] = 0;
        __syncthreads();

        const unsigned int pmask = (pass == 0) ? 0u : (0xFFFFFFFFu << (32 - 8 * pass));
        const unsigned int pref  = s_prefix;

        for (int i = t; i < 4096; i += 1024) {       // padded for full-warp match
            unsigned int key = 0x100u;
            if (i < S) {
                unsigned int u = uvals[i];
                if ((u & pmask) == pref) key = (u >> shift) & 0xFFu;
            }
            unsigned int grp = __match_any_sync(0xFFFFFFFFu, key);
            if (key != 0x100u && lane == (__ffs(grp) - 1))
                atomicAdd(&hist[key], __popc(grp));
        }
        __syncthreads();

        int v = 0;
        if (t < 256) {
            v = hist[t];
            #pragma unroll
            for (int d = 1; d < 32; d <<= 1) {
                int n = __shfl_up_sync(0xFFFFFFFFu, v, d);
                if (lane >= d) v += n;
            }
            if (lane == 31) warpTot[t >> 5] = v;
        }
        __syncthreads();
        if (t < 8) {
            int wv = warpTot[t];
            #pragma unroll
            for (int d = 1; d < 8; d <<= 1) {
                int n = __shfl_up_sync(0xFFu, wv, d);
                if (t >= d) wv += n;
            }
            warpTot[t] = wv;
        }
        __syncthreads();
        if (t < 256) {
            int incl = v + ((t >= 32) ? warpTot[(t >> 5) - 1] : 0);
            int excl = incl - hist[t];
            int r = s_r;
            if (excl <= r && r < incl) {
                s_r      = r - excl;
                s_less  += excl;
                s_prefix = pref | ((unsigned int)t << shift);
            }
        }
        __syncthreads();
    }

    const unsigned int T = s_prefix;
    const int zeroTies = RNUM - s_less;     // # of ties (==T) to zero, ascending index

    for (int i = t; i < S; i += 1024) {
        if (uvals[i] == T) {
            int p = atomicAdd(&tieCount, 1);
            if (p < 256) tieIdx[p] = i;
        }
    }
    __syncthreads();

    if (t == 0) {
        int tc = tieCount < 256 ? tieCount : 256;
        for (int i = 1; i < tc; ++i) {       // expected tc == 1
            int v2 = tieIdx[i], j = i - 1;
            while (j >= 0 && tieIdx[j] > v2) { tieIdx[j + 1] = tieIdx[j]; --j; }
            tieIdx[j + 1] = v2;
        }
        int z = zeroTies < tc ? zeroTies : tc;
        g_T[b] = T;
        g_bound[b] = (z <= 0) ? 0 : (tieIdx[z - 1] + 1);
    }
}

// ---------------------------------------------------------------------------
// Kernel 4: broadcast with inline mask (write-roofline kernel).
// ---------------------------------------------------------------------------
__global__ void bcast(float* __restrict__ out) {
    int gid = blockIdx.x * blockDim.x + threadIdx.x;   // 0 .. BATCH*CHAN*S4-1
    int row = gid / S4;          // b*256 + c
    int s4  = gid % S4;
    int b   = row >> 8;

    uint4 u = __ldg(reinterpret_cast<const uint4*>(g_uvals) + b * S4 + s4);
    unsigned int T = __ldg(&g_T[b]);
    int bound      = __ldg(&g_bound[b]);
    int i0 = s4 * 4;

    float4 v;
    v.x = (u.x < T || (u.x == T && (i0 + 0) < bound)) ? 0.f : __uint_as_float(u.x);
    v.y = (u.y < T || (u.y == T && (i0 + 1) < bound)) ? 0.f : __uint_as_float(u.y);
    v.z = (u.z < T || (u.z == T && (i0 + 2) < bound)) ? 0.f : __uint_as_float(u.z);
    v.w = (u.w < T || (u.w == T && (i0 + 3) < bound)) ? 0.f : __uint_as_float(u.w);
    reinterpret_cast<float4*>(out)[gid] = v;
}

// ---------------------------------------------------------------------------
extern "C" void kernel_launch(void* const* d_in, const int* in_sizes, int n_in,
                              void* d_out, int out_size) {
    const float* x = (const float*)d_in[0];   // [32,256,56,56]
    const float* w = (const float*)d_in[1];   // [1,2,3,3]
    float* out = (float*)d_out;               // [32,256,56,56]

    pool_partial<<<(QSPLIT * BATCH * S4) / 256, 256>>>(x);   // 1568 blocks
    conv_sig<<<BATCH * RB, 448>>>(w);                        // 224 blocks
    select_thresh<<<BATCH, 1024>>>();                        // 32 blocks
    bcast<<<(BATCH * CHAN * S4) / 256, 256>>>(out);          // 25088 blocks
}

// round 5
// speedup vs baseline: 1.0780x; 1.0780x over previous
#include <cuda_runtime.h>
#include <stdint.h>
#include <math.h>

#define BATCH 32
#define CHAN  256
#define HH    56
#define WW    56
#define S     (HH*WW)        // 3136
#define S4    (S/4)          // 784
#define QSPLIT 8
#define CQ    (CHAN/QSPLIT)  // 32
#define RNUM  1568           // removed_num = round(3136*0.5)
#define RB    7              // row-blocks per batch (8 rows each)
#define CSPL  4              // channel splits in bcast
#define CPB   (CHAN/CSPL)    // 64 channels per bcast block

// scratch (no cudaMalloc allowed)
__device__ __align__(16) float        g_part_max[QSPLIT*BATCH*S];
__device__ __align__(16) float        g_part_sum[QSPLIT*BATCH*S];
__device__ __align__(16) unsigned int g_uvals[BATCH*S];
__device__ __align__(16) float        g_y[BATCH*S];

// ---------------------------------------------------------------------------
// Kernel 1: partial channel max/sum. 784 blocks x 256 threads.
// Read-roofline kernel (~103 MB in, 6.4 MB partials out).
// ---------------------------------------------------------------------------
__global__ void pool_partial(const float* __restrict__ x) {
    int gid = blockIdx.x * blockDim.x + threadIdx.x;
    int q   = gid / (BATCH * S4);
    int rem = gid % (BATCH * S4);
    int b   = rem / S4;
    int s4  = rem % S4;

    const float4* p = reinterpret_cast<const float4*>(x)
                    + (size_t)(b * CHAN + q * CQ) * S4 + s4;

    float4 mx = make_float4(-INFINITY, -INFINITY, -INFINITY, -INFINITY);
    float4 sm = make_float4(0.f, 0.f, 0.f, 0.f);

    #pragma unroll 8
    for (int c = 0; c < CQ; ++c) {
        float4 v = __ldcs(p + (size_t)c * S4);   // read-once: stream past L2
        mx.x = fmaxf(mx.x, v.x); mx.y = fmaxf(mx.y, v.y);
        mx.z = fmaxf(mx.z, v.z); mx.w = fmaxf(mx.w, v.w);
        sm.x += v.x; sm.y += v.y; sm.z += v.z; sm.w += v.w;
    }

    int o = (q * BATCH + b) * S4 + s4;
    reinterpret_cast<float4*>(g_part_max)[o] = mx;
    reinterpret_cast<float4*>(g_part_sum)[o] = sm;
}

// ---------------------------------------------------------------------------
// Kernel 2: combine partials + 3x3 conv + sigmoid -> g_uvals. 224 blocks
// (BATCH*RB), 448 threads; each block owns an 8-row slab + 1-row halo.
// Partials L2-hot, full-chip parallel.
// ---------------------------------------------------------------------------
__global__ void __launch_bounds__(448) conv_sig(const float* __restrict__ w) {
    __shared__ float pm[10 * WW];
    __shared__ float pa[10 * WW];
    __shared__ float ws[18];

    const int b  = blockIdx.x / RB;
    const int rb = blockIdx.x % RB;
    const int t  = threadIdx.x;
    const int row0 = rb * 8 - 1;            // global row of smem row 0

    if (t < 18) ws[t] = w[t];

    const float inv = 1.0f / (float)CHAN;
    for (int j = t; j < 10 * WW; j += 448) {
        int grow = row0 + j / WW;
        int col  = j % WW;
        float mx = 0.f, sm = 0.f;
        if (grow >= 0 && grow < HH) {
            int base = grow * WW + col;
            mx = -INFINITY;
            #pragma unroll
            for (int q = 0; q < QSPLIT; ++q) {
                int o = (q * BATCH + b) * S + base;
                mx = fmaxf(mx, g_part_max[o]);
                sm += g_part_sum[o];
            }
            sm *= inv;
        }
        pm[j] = mx;
        pa[j] = sm;
    }
    __syncthreads();

    const int ohl = t / WW;                 // 0..7 local row
    const int ow  = t % WW;
    const int oh  = rb * 8 + ohl;

    float acc = 0.f;
    #pragma unroll
    for (int ky = 0; ky < 3; ++ky) {
        int ih = oh + ky - 1;
        if (ih < 0 || ih >= HH) continue;
        int lr = ohl + ky;
        #pragma unroll
        for (int kx = 0; kx < 3; ++kx) {
            int iw = ow + kx - 1;
            if (iw < 0 || iw >= WW) continue;
            int ii = lr * WW + iw;
            acc = fmaf(pm[ii], ws[ky * 3 + kx], acc);
            acc = fmaf(pa[ii], ws[9 + ky * 3 + kx], acc);
        }
    }
    float y = 1.0f / (1.0f + expf(-acc));
    g_uvals[b * S + oh * WW + ow] = __float_as_uint(y);
}

// ---------------------------------------------------------------------------
// Kernel 3: per-batch exact radix select of rank RNUM-1, then write the
// MASKED map to g_y (float). One block per batch, 1024 threads.
// ---------------------------------------------------------------------------
__global__ void __launch_bounds__(1024, 1) select_mask() {
    __shared__ unsigned int uvals[S];
    __shared__ int hist[256];
    __shared__ int warpTot[8];
    __shared__ unsigned int s_prefix;
    __shared__ int s_r, s_less;
    __shared__ int tieIdx[256];
    __shared__ int tieCount;
    __shared__ int s_bound;

    const int b = blockIdx.x;
    const int t = threadIdx.x;
    const int lane = t & 31;

    for (int i = t; i < S; i += 1024) uvals[i] = g_uvals[b * S + i];
    if (t == 0) { s_r = RNUM - 1; s_less = 0; s_prefix = 0u; tieCount = 0; }
    __syncthreads();

    #pragma unroll
    for (int pass = 0; pass < 4; ++pass) {
        const int shift = 24 - 8 * pass;
        if (t < 256) hist[t] = 0;
        __syncthreads();

        const unsigned int pmask = (pass == 0) ? 0u : (0xFFFFFFFFu << (32 - 8 * pass));
        const unsigned int pref  = s_prefix;

        for (int i = t; i < 4096; i += 1024) {       // padded for full-warp match
            unsigned int key = 0x100u;
            if (i < S) {
                unsigned int u = uvals[i];
                if ((u & pmask) == pref) key = (u >> shift) & 0xFFu;
            }
            unsigned int grp = __match_any_sync(0xFFFFFFFFu, key);
            if (key != 0x100u && lane == (__ffs(grp) - 1))
                atomicAdd(&hist[key], __popc(grp));
        }
        __syncthreads();

        int v = 0;
        if (t < 256) {
            v = hist[t];
            #pragma unroll
            for (int d = 1; d < 32; d <<= 1) {
                int n = __shfl_up_sync(0xFFFFFFFFu, v, d);
                if (lane >= d) v += n;
            }
            if (lane == 31) warpTot[t >> 5] = v;
        }
        __syncthreads();
        if (t < 8) {
            int wv = warpTot[t];
            #pragma unroll
            for (int d = 1; d < 8; d <<= 1) {
                int n = __shfl_up_sync(0xFFu, wv, d);
                if (t >= d) wv += n;
            }
            warpTot[t] = wv;
        }
        __syncthreads();
        if (t < 256) {
            int incl = v + ((t >= 32) ? warpTot[(t >> 5) - 1] : 0);
            int excl = incl - hist[t];
            int r = s_r;
            if (excl <= r && r < incl) {
                s_r      = r - excl;
                s_less  += excl;
                s_prefix = pref | ((unsigned int)t << shift);
            }
        }
        __syncthreads();
    }

    const unsigned int T = s_prefix;
    const int zeroTies = RNUM - s_less;     // # ties (==T) to zero, ascending index

    for (int i = t; i < S; i += 1024) {
        if (uvals[i] == T) {
            int p = atomicAdd(&tieCount, 1);
            if (p < 256) tieIdx[p] = i;
        }
    }
    __syncthreads();

    if (t == 0) {
        int tc = tieCount < 256 ? tieCount : 256;
        for (int i = 1; i < tc; ++i) {       // expected tc == 1
            int v2 = tieIdx[i], j = i - 1;
            while (j >= 0 && tieIdx[j] > v2) { tieIdx[j + 1] = tieIdx[j]; --j; }
            tieIdx[j + 1] = v2;
        }
        int z = zeroTies < tc ? zeroTies : tc;
        s_bound = (z <= 0) ? 0 : (tieIdx[z - 1] + 1);
    }
    __syncthreads();

    const int bound = s_bound;
    float* yb = g_y + b * S;
    for (int i = t; i < S; i += 1024) {
        unsigned int u = uvals[i];
        float v = __uint_as_float(u);
        if (u < T || (u == T && i < bound)) v = 0.0f;
        yb[i] = v;
    }
}

// ---------------------------------------------------------------------------
// Kernel 4: broadcast masked map to all channels (write-roofline kernel).
// Each thread: 1 float4 load (L2-hot), 64 streamed float4 stores.
// grid = (4 spatial chunks, CSPL, BATCH), block = 256.
// ---------------------------------------------------------------------------
__global__ void __launch_bounds__(256) bcast(float* __restrict__ out) {
    const int b  = blockIdx.z;
    const int cq = blockIdx.y;
    const int s4 = blockIdx.x * 256 + threadIdx.x;
    if (s4 >= S4) return;

    float4 v = __ldg(reinterpret_cast<const float4*>(g_y) + b * S4 + s4);

    float4* p = reinterpret_cast<float4*>(out)
              + ((size_t)(b * CHAN + cq * CPB)) * S4 + s4;
    #pragma unroll 8
    for (int c = 0; c < CPB; ++c) {
        __stcs(p, v);
        p += S4;
    }
}

// ---------------------------------------------------------------------------
extern "C" void kernel_launch(void* const* d_in, const int* in_sizes, int n_in,
                              void* d_out, int out_size) {
    const float* x = (const float*)d_in[0];   // [32,256,56,56]
    const float* w = (const float*)d_in[1];   // [1,2,3,3]
    float* out = (float*)d_out;               // [32,256,56,56]

    pool_partial<<<(QSPLIT * BATCH * S4) / 256, 256>>>(x);   // 784 blocks
    conv_sig<<<BATCH * RB, 448>>>(w);                        // 224 blocks
    select_mask<<<BATCH, 1024>>>();                          // 32 blocks
    bcast<<<dim3(4, CSPL, BATCH), 256>>>(out);               // 512 blocks
}

// round 6
// speedup vs baseline: 1.2477x; 1.1574x over previous
#include <cuda_runtime.h>
#include <stdint.h>
#include <math.h>

#define BATCH 32
#define CHAN  256
#define HH    56
#define WW    56
#define S     (HH*WW)        // 3136
#define S4    (S/4)          // 784
#define QSPLIT 8
#define CQ    (CHAN/QSPLIT)  // 32
#define RNUM  1568           // removed_num = round(3136*0.5)

// scratch (no cudaMalloc allowed)
__device__ __align__(16) float g_part_max[QSPLIT*BATCH*S];
__device__ __align__(16) float g_part_sum[QSPLIT*BATCH*S];
__device__ __align__(16) float g_y[BATCH*S];

// ---------------------------------------------------------------------------
// Kernel 1: partial channel max/sum. 784 blocks x 256 threads.
// Read-roofline kernel (~103 MB in, 6.4 MB partials out). At measured ceiling.
// ---------------------------------------------------------------------------
__global__ void pool_partial(const float* __restrict__ x) {
    int gid = blockIdx.x * blockDim.x + threadIdx.x;
    int q   = gid / (BATCH * S4);
    int rem = gid % (BATCH * S4);
    int b   = rem / S4;
    int s4  = rem % S4;

    const float4* p = reinterpret_cast<const float4*>(x)
                    + (size_t)(b * CHAN + q * CQ) * S4 + s4;

    float4 mx = make_float4(-INFINITY, -INFINITY, -INFINITY, -INFINITY);
    float4 sm = make_float4(0.f, 0.f, 0.f, 0.f);

    #pragma unroll 8
    for (int c = 0; c < CQ; ++c) {
        float4 v = __ldcs(p + (size_t)c * S4);   // read-once: stream past L2
        mx.x = fmaxf(mx.x, v.x); mx.y = fmaxf(mx.y, v.y);
        mx.z = fmaxf(mx.z, v.z); mx.w = fmaxf(mx.w, v.w);
        sm.x += v.x; sm.y += v.y; sm.z += v.z; sm.w += v.w;
    }

    int o = (q * BATCH + b) * S4 + s4;
    reinterpret_cast<float4*>(g_part_max)[o] = mx;
    reinterpret_cast<float4*>(g_part_sum)[o] = sm;
}

// ---------------------------------------------------------------------------
// Kernel 2 (fused middle): per batch -> combine partials, conv+sigmoid,
// barrier-lean exact radix select, masked write to g_y.
// One block per batch, 1024 threads. 3 barriers per radix pass; the 256-bin
// scan + bin-select is done by warp 0 alone (shfl, no block scan).
// ---------------------------------------------------------------------------
__global__ void __launch_bounds__(1024, 1) fused_mid(const float* __restrict__ w) {
    __shared__ float pm[S];
    __shared__ float pa[S];
    __shared__ unsigned int uvals[S];     // sigmoid bits; >0 so uint order == float order
    __shared__ int hist[256];
    __shared__ float ws[18];
    __shared__ unsigned int s_prefix;
    __shared__ int s_r, s_less;
    __shared__ int tieIdx[256];
    __shared__ int tieCount;
    __shared__ int s_bound;

    const int b = blockIdx.x;
    const int t = threadIdx.x;
    const int lane = t & 31;

    if (t < 18) ws[t] = w[t];
    if (t < 256) hist[t] = 0;             // pre-clear for pass 0
    if (t == 0) { s_r = RNUM - 1; s_less = 0; s_prefix = 0u; tieCount = 0; }

    // --- combine QSPLIT partials -> pooled max/avg in smem ---
    const float inv = 1.0f / (float)CHAN;
    for (int i = t; i < S; i += 1024) {
        float mx = -INFINITY, sm = 0.f;
        #pragma unroll
        for (int q = 0; q < QSPLIT; ++q) {
            int o = (q * BATCH + b) * S + i;
            mx = fmaxf(mx, g_part_max[o]);
            sm += g_part_sum[o];
        }
        pm[i] = mx;
        pa[i] = sm * inv;
    }
    __syncthreads();

    // --- 3x3 conv (2ch->1ch, pad 1, cross-correlation OIHW) + sigmoid ---
    for (int i = t; i < S; i += 1024) {
        int oh = i / WW, ow = i % WW;
        float acc = 0.f;
        #pragma unroll
        for (int ky = 0; ky < 3; ++ky) {
            int ih = oh + ky - 1;
            if (ih < 0 || ih >= HH) continue;
            #pragma unroll
            for (int kx = 0; kx < 3; ++kx) {
                int iw = ow + kx - 1;
                if (iw < 0 || iw >= WW) continue;
                int ii = ih * WW + iw;
                acc = fmaf(pm[ii], ws[ky * 3 + kx], acc);
                acc = fmaf(pa[ii], ws[9 + ky * 3 + kx], acc);
            }
        }
        uvals[i] = __float_as_uint(1.0f / (1.0f + expf(-acc)));
    }
    __syncthreads();

    // --- 4-pass radix select, 3 barriers per pass ---
    #pragma unroll
    for (int pass = 0; pass < 4; ++pass) {
        const int shift = 24 - 8 * pass;
        const unsigned int pmask = (pass == 0) ? 0u : (0xFFFFFFFFu << (32 - 8 * pass));
        const unsigned int pref  = s_prefix;

        for (int i = t; i < S; i += 1024) {
            unsigned int u = uvals[i];
            if ((u & pmask) == pref)
                atomicAdd(&hist[(u >> shift) & 0xFF], 1);
        }
        __syncthreads();

        // warp 0 alone: serial 8-bin sums + shfl scan + bin select
        if (t < 32) {
            int base = t * 8;
            int h0 = hist[base + 0], h1 = hist[base + 1];
            int h2 = hist[base + 2], h3 = hist[base + 3];
            int h4 = hist[base + 4], h5 = hist[base + 5];
            int h6 = hist[base + 6], h7 = hist[base + 7];
            int tot = h0 + h1 + h2 + h3 + h4 + h5 + h6 + h7;

            int ex = tot;                         // -> exclusive prefix of lane totals
            #pragma unroll
            for (int d = 1; d < 32; d <<= 1) {
                int n = __shfl_up_sync(0xFFFFFFFFu, ex, d);
                if (lane >= d) ex += n;
            }
            ex -= tot;

            int r = s_r;
            if (ex <= r && r < ex + tot) {        // exactly one lane matches
                int cum = ex, bin = base;
                int hh[8] = {h0,h1,h2,h3,h4,h5,h6,h7};
                #pragma unroll
                for (int k = 0; k < 8; ++k) {
                    if (cum + hh[k] > r) { bin = base + k; break; }
                    cum += hh[k];
                }
                s_r      = r - cum;
                s_less  += cum;
                s_prefix = pref | ((unsigned int)bin << shift);
            }
        }
        __syncthreads();

        if (pass < 3) {                           // clear for next pass
            if (t < 256) hist[t] = 0;
            __syncthreads();
        }
    }

    const unsigned int T = s_prefix;
    const int zeroTies = RNUM - s_less;           // # ties (==T) to zero, ascending index

    for (int i = t; i < S; i += 1024) {
        if (uvals[i] == T) {
            int p = atomicAdd(&tieCount, 1);
            if (p < 256) tieIdx[p] = i;
        }
    }
    __syncthreads();

    if (t == 0) {
        int tc = tieCount < 256 ? tieCount : 256;
        for (int i = 1; i < tc; ++i) {            // expected tc == 1
            int v2 = tieIdx[i], j = i - 1;
            while (j >= 0 && tieIdx[j] > v2) { tieIdx[j + 1] = tieIdx[j]; --j; }
            tieIdx[j + 1] = v2;
        }
        int z = zeroTies < tc ? zeroTies : tc;
        s_bound = (z <= 0) ? 0 : (tieIdx[z - 1] + 1);
    }
    __syncthreads();

    const int bound = s_bound;
    float* yb = g_y + b * S;
    for (int i = t; i < S; i += 1024) {
        unsigned int u = uvals[i];
        float v = __uint_as_float(u);
        if (u < T || (u == T && i < bound)) v = 0.0f;
        yb[i] = v;
    }
}

// ---------------------------------------------------------------------------
// Kernel 3: broadcast masked map to all 256 channels (write-roofline kernel).
// One float4 load (L2-hot) + one float4 store per thread.
// ---------------------------------------------------------------------------
__global__ void bcast(float* __restrict__ out) {
    int gid = blockIdx.x * blockDim.x + threadIdx.x;   // 0 .. BATCH*CHAN*S4-1
    int row = gid / S4;          // b*256 + c
    int s4  = gid % S4;
    int b   = row >> 8;
    float4 v = __ldg(reinterpret_cast<const float4*>(g_y) + b * S4 + s4);
    reinterpret_cast<float4*>(out)[gid] = v;
}

// ---------------------------------------------------------------------------
extern "C" void kernel_launch(void* const* d_in, const int* in_sizes, int n_in,
                              void* d_out, int out_size) {
    const float* x = (const float*)d_in[0];   // [32,256,56,56]
    const float* w = (const float*)d_in[1];   // [1,2,3,3]
    float* out = (float*)d_out;               // [32,256,56,56]

    pool_partial<<<(QSPLIT * BATCH * S4) / 256, 256>>>(x);   // 784 blocks
    fused_mid<<<BATCH, 1024>>>(w);                           // 32 blocks
    bcast<<<(BATCH * CHAN * S4) / 256, 256>>>(out);          // 25088 blocks
}